// round 11
// baseline (speedup 1.0000x reference)
#include <cuda_runtime.h>
#include <cuda_bf16.h>
#include <cuda_fp8.h>
#include <math.h>
#include <stdint.h>

#define NN 200
#define DD 128
#define PAD_IDX 100000
#define VP1 100001
#define NTHR 256
#define NWARP 8

// ---------------- device scratch (no runtime allocation allowed) ----------------
__device__ unsigned char g_embF[(size_t)VP1 * 128];   // fp8 e4m3 embeddings x16 (12.8 MB)
__device__ uint2 g_WfragF[8 * 8 * 16 * 32];           // fp8 B fragments (256 KB)
__device__ float g_Wcomb[4 * 256 * 128];              // [h][f][d] Wv folded with Ww
__device__ float g_WheadT[128 * 128];                 // [e][d] Whead transposed

// ================= helpers =================
__device__ __forceinline__ uint32_t smem_u32(const void* p) {
    uint32_t a;
    asm("{ .reg .u64 t; cvta.to.shared.u64 t, %1; cvt.u32.u64 %0, t; }" : "=r"(a) : "l"(p));
    return a;
}
__device__ __forceinline__ void ldsm_x4(uint32_t* r, uint32_t a) {
    asm volatile("ldmatrix.sync.aligned.m8n8.x4.shared.b16 {%0,%1,%2,%3}, [%4];"
                 : "=r"(r[0]), "=r"(r[1]), "=r"(r[2]), "=r"(r[3]) : "r"(a));
}
__device__ __forceinline__ void ldsm_x2(uint32_t* r, uint32_t a) {
    asm volatile("ldmatrix.sync.aligned.m8n8.x2.shared.b16 {%0,%1}, [%2];"
                 : "=r"(r[0]), "=r"(r[1]) : "r"(a));
}
// fp8 e4m3 mma: m16n8k32, fp32 accum
__device__ __forceinline__ void mma_fp8(float* c, const uint32_t* a, uint32_t b0, uint32_t b1) {
    asm volatile("mma.sync.aligned.m16n8k32.row.col.f32.e4m3.e4m3.f32 "
                 "{%0,%1,%2,%3}, {%4,%5,%6,%7}, {%8,%9}, {%0,%1,%2,%3};"
                 : "+f"(c[0]), "+f"(c[1]), "+f"(c[2]), "+f"(c[3])
                 : "r"(a[0]), "r"(a[1]), "r"(a[2]), "r"(a[3]), "r"(b0), "r"(b1));
}
__device__ __forceinline__ unsigned short fp8x2(float lo, float hi) {
    return (unsigned short)__nv_cvt_float2_to_fp8x2(make_float2(lo, hi),
                                                    __NV_SATFINITE, __NV_E4M3);
}
__device__ __forceinline__ uint4 pack16_fp8_x16(float4 v0, float4 v1, float4 v2, float4 v3) {
    uint4 o;
    o.x = (uint32_t)fp8x2(v0.x * 16.f, v0.y * 16.f) | ((uint32_t)fp8x2(v0.z * 16.f, v0.w * 16.f) << 16);
    o.y = (uint32_t)fp8x2(v1.x * 16.f, v1.y * 16.f) | ((uint32_t)fp8x2(v1.z * 16.f, v1.w * 16.f) << 16);
    o.z = (uint32_t)fp8x2(v2.x * 16.f, v2.y * 16.f) | ((uint32_t)fp8x2(v2.z * 16.f, v2.w * 16.f) << 16);
    o.w = (uint32_t)fp8x2(v3.x * 16.f, v3.y * 16.f) | ((uint32_t)fp8x2(v3.z * 16.f, v3.w * 16.f) << 16);
    return o;
}

// ---------------- prep kernels ----------------
__global__ void prep_wcomb(const float* __restrict__ Wv, const float* __restrict__ Ww) {
    int f = blockIdx.x, h = blockIdx.y, d2 = threadIdx.x;
    float a = 0.f;
    for (int d = 0; d < 128; d++)
        a = fmaf(Wv[(h * 128 + d) * 256 + f], Ww[d2 * 512 + h * 128 + d], a);
    g_Wcomb[(h * 256 + f) * 128 + d2] = a;
}
__global__ void prep_wheadT(const float* __restrict__ Whead) {
    g_WheadT[blockIdx.x * 128 + threadIdx.x] = Whead[threadIdx.x * 128 + blockIdx.x];
}
__global__ void prep_embF(const float* __restrict__ emb) {
    size_t i = ((size_t)blockIdx.x * 256 + threadIdx.x) * 16;
    if (i < (size_t)VP1 * 128) {
        const float4* s = reinterpret_cast<const float4*>(emb + i);
        *reinterpret_cast<uint4*>(g_embF + i) = pack16_fp8_x16(s[0], s[1], s[2], s[3]);
    }
}
__global__ void prep_wfragF(const float* __restrict__ Wk, const float* __restrict__ Wq) {
    __shared__ unsigned char Wsh[128 * 48];
    int t = blockIdx.x, ks = blockIdx.y, lane = threadIdx.x;
    const float* Wsrc = ((t < 4) ? Wk : Wq) + (size_t)(t & 3) * 128 * 256;
    for (int i = lane; i < 256; i += 32) {
        int rn = i >> 1, half = i & 1;
        const float4* s = reinterpret_cast<const float4*>(Wsrc + rn * 256 + ks * 32 + half * 16);
        *reinterpret_cast<uint4*>(&Wsh[rn * 48 + half * 16]) =
            pack16_fp8_x16(s[0], s[1], s[2], s[3]);
    }
    __syncwarp();
    uint32_t base = smem_u32(Wsh) + (uint32_t)((lane & 7) * 48 + ((lane >> 3) & 1) * 16);
    for (int f = 0; f < 16; f++) {
        uint32_t bb[2];
        ldsm_x2(bb, base + f * (8 * 48));
        g_WfragF[((t * 8 + ks) * 16 + f) * 32 + lane] = make_uint2(bb[0], bb[1]);
    }
}

// ---------------- the fused mega-kernel (fp8 GEMMs, 256 thr, no spills) ------
// 8 warps; warp w owns M-tiles {w, w+8} (13 tiles of 16 rows), processed
// SEQUENTIALLY so the 104-reg score fragment array never coexists twice.
// 256 threads -> 256-reg/thread ceiling -> c[26][4] stays in registers
// (at 416 threads the 157-reg cap spilled it to local; R9/R10 evidence).
#define XSB 272
#define KQB 144
#define OFF_X   0
#define OFF_K   56576
#define OFF_Q   86528
#define OFF_WS4 116480
#define OFF_MSK 119680
#define OFF_YS  120512
#define OFF_ES  124608
#define OFF_PA2 125120
#define OFF_RED 126144
#define OFF_IDX 126208
#define SM_TOT  127808

__global__ void __launch_bounds__(NTHR, 1)
mega(const int* __restrict__ ep, const int* __restrict__ lconn,
     const int* __restrict__ rconn, const float* __restrict__ emb,
     const float* __restrict__ lnw, const float* __restrict__ lnb,
     float* __restrict__ out) {
    extern __shared__ char smem[];
    uint32_t sb = smem_u32(smem);
    float* ws4 = reinterpret_cast<float*>(smem + OFF_WS4);   // [4][200]
    float* msk = reinterpret_cast<float*>(smem + OFF_MSK);
    float* ysm = reinterpret_cast<float*>(smem + OFF_YS);    // [4][256]
    float* es  = reinterpret_cast<float*>(smem + OFF_ES);
    float* pa2 = reinterpret_cast<float*>(smem + OFF_PA2);
    float* red = reinterpret_cast<float*>(smem + OFF_RED);
    int*   reli = reinterpret_cast<int*>(smem + OFF_IDX);
    int*   enti = reli + 200;

    int tid = threadIdx.x, w = tid >> 5, lane = tid & 31;
    int sid = blockIdx.x, b = sid >> 1;
    const int* conn = (sid & 1) ? rconn : lconn;

    // gather X fp8 (rows >= 200 zeroed)
    for (int i = tid; i < 208 * 16; i += NTHR) {
        int n = i >> 4, q = i & 15;
        uint4 v = make_uint4(0u, 0u, 0u, 0u);
        if (n < 200) {
            int idx = conn[(b * NN + n) * 2 + (q >> 3)];
            v = *reinterpret_cast<const uint4*>(g_embF + (size_t)idx * 128 + (q & 7) * 16);
        }
        *reinterpret_cast<uint4*>(smem + OFF_X + n * XSB + q * 16) = v;
    }
    for (int i = tid; i < 208; i += NTHR) {
        if (i < 200) {
            int2 cc = reinterpret_cast<const int2*>(conn)[b * NN + i];
            reli[i] = cc.x; enti[i] = cc.y;
            msk[i] = (cc.x == PAD_IDX) ? 1.f : 0.f;
        } else {
            msk[i] = 1.f;
        }
    }
    for (int i = tid; i < 800; i += NTHR) ws4[i] = 0.f;
    for (int i = tid; i < 1024; i += NTHR) ysm[i] = 0.f;
    if (tid < 128) es[tid] = emb[(size_t)ep[b * 2 + (sid & 1)] * DD + tid];
    __syncthreads();

    uint32_t qb = sb + OFF_Q + (uint32_t)((lane & 7) * KQB + ((lane >> 3) & 1) * 16);
    int d0 = (lane & 3) * 2;
    // emb,W scaled x16 each -> S_mma = 65536 * S_true
    const float scale = 0.08838834764831845f / 65536.0f;

    for (int h = 0; h < 4; h++) {
        // ---- project K_h (kq=0) and Q_h (kq=1) into SMEM fp8 ----
#pragma unroll 1
        for (int kq = 0; kq < 2; kq++) {
            int t = kq * 4 + h;
            const uint2* wf = g_WfragF + (size_t)t * 4096 + lane;
            char* dst = smem + (kq ? OFF_Q : OFF_K);
#pragma unroll 1
            for (int mt = w; mt < 13; mt += NWARP) {
                uint32_t xa = sb + OFF_X +
                    (uint32_t)((mt * 16 + (lane & 15)) * XSB + (lane >> 4) * 16);
                int r0 = mt * 16 + (lane >> 2);
                float c[16][4];
#pragma unroll
                for (int f = 0; f < 16; f++) { c[f][0] = 0.f; c[f][1] = 0.f; c[f][2] = 0.f; c[f][3] = 0.f; }
#pragma unroll 1
                for (int ks = 0; ks < 8; ks++) {
                    uint32_t a[4];
                    ldsm_x4(a, xa + ks * 32);
                    const uint2* wfk = wf + ks * 512;
#pragma unroll
                    for (int f = 0; f < 16; f++) {
                        uint2 bv = __ldg(wfk + f * 32);
                        mma_fp8(c[f], a, bv.x, bv.y);
                    }
                }
#pragma unroll
                for (int f = 0; f < 16; f++) {
                    *reinterpret_cast<unsigned short*>(dst + r0 * KQB + f * 8 + d0) =
                        fp8x2(c[f][0], c[f][1]);
                    *reinterpret_cast<unsigned short*>(dst + (r0 + 8) * KQB + f * 8 + d0) =
                        fp8x2(c[f][2], c[f][3]);
                }
            }
        }
        __syncthreads();

        // ---- attention: scores (fp8 mma), mask, softmax, column sums -> ws4[h] ----
        {
            float* wsh = ws4 + h * 200;
            int mc = (lane & 3) * 2;
#pragma unroll 1
            for (int mt = w; mt < 13; mt += NWARP) {
                uint32_t ka = sb + OFF_K +
                    (uint32_t)((mt * 16 + (lane & 15)) * KQB + (lane >> 4) * 16);
                float c[26][4];
#pragma unroll
                for (int f = 0; f < 26; f++) { c[f][0] = 0.f; c[f][1] = 0.f; c[f][2] = 0.f; c[f][3] = 0.f; }
#pragma unroll 1
                for (int ks = 0; ks < 4; ks++) {
                    uint32_t a[4];
                    ldsm_x4(a, ka + ks * 32);
                    uint32_t bcur[2], bnxt[2];
                    ldsm_x2(bcur, qb + ks * 32);
#pragma unroll
                    for (int f = 0; f < 26; f++) {
                        if (f < 25) ldsm_x2(bnxt, qb + (f + 1) * (8 * KQB) + ks * 32);
                        mma_fp8(c[f], a, bcur[0], bcur[1]);
                        bcur[0] = bnxt[0]; bcur[1] = bnxt[1];
                    }
                }
                int n0 = mt * 16 + (lane >> 2);
#pragma unroll
                for (int p = 0; p < 2; p++) {
                    int nn = n0 + p * 8;
                    float rm = msk[nn];
                    float rmax = -3.0e38f;
#pragma unroll
                    for (int f = 0; f < 26; f++) {
#pragma unroll
                        for (int j = 0; j < 2; j++) {
                            int m = f * 8 + mc + j;
                            float s;
                            if (m >= 200)                        s = -1e30f;
                            else if (rm > 0.5f || msk[m] > 0.5f) s = -1e9f;
                            else                                 s = c[f][2 * p + j] * scale;
                            c[f][2 * p + j] = s;
                            rmax = fmaxf(rmax, s);
                        }
                    }
                    rmax = fmaxf(rmax, __shfl_xor_sync(0xffffffffu, rmax, 1));
                    rmax = fmaxf(rmax, __shfl_xor_sync(0xffffffffu, rmax, 2));
                    float Z = 0.f;
#pragma unroll
                    for (int f = 0; f < 26; f++) {
#pragma unroll
                        for (int j = 0; j < 2; j++) {
                            float e = __expf(c[f][2 * p + j] - rmax);
                            c[f][2 * p + j] = e;
                            Z += e;
                        }
                    }
                    Z += __shfl_xor_sync(0xffffffffu, Z, 1);
                    Z += __shfl_xor_sync(0xffffffffu, Z, 2);
                    float inv = (nn < 200) ? (1.f / Z) : 0.f;
#pragma unroll
                    for (int f = 0; f < 26; f++) {
                        c[f][2 * p + 0] *= inv;
                        c[f][2 * p + 1] *= inv;
                    }
                }
#pragma unroll
                for (int f = 0; f < 26; f++) {
#pragma unroll
                    for (int j = 0; j < 2; j++) {
                        float v = c[f][j] + c[f][2 + j];
                        v += __shfl_xor_sync(0xffffffffu, v, 4);
                        v += __shfl_xor_sync(0xffffffffu, v, 8);
                        v += __shfl_xor_sync(0xffffffffu, v, 16);
                        if ((lane >> 2) == 0) {
                            int m = f * 8 + mc + j;
                            if (m < 200) atomicAdd(wsh + m, v);
                        }
                    }
                }
            }
        }
        __syncthreads();   // K/Q reads done before next proj; ws4[h] complete
    }

    // ---- single y pass: each emb row loaded ONCE, 4 head weights fused ----
    {
        float acc[4][8];
#pragma unroll
        for (int hh = 0; hh < 4; hh++)
#pragma unroll
            for (int k = 0; k < 8; k++) acc[hh][k] = 0.f;
#pragma unroll 1
        for (int mt = w; mt < 13; mt += NWARP) {
            int m0 = mt * 16;
            for (int i = 0; i < 16; i++) {
                int m = m0 + i;
                if (m < 200) {
                    float w0 = ws4[m], w1 = ws4[200 + m], w2 = ws4[400 + m], w3 = ws4[600 + m];
                    const float* er = emb + (size_t)reli[m] * DD;
                    const float* ee = emb + (size_t)enti[m] * DD;
#pragma unroll
                    for (int k = 0; k < 4; k++) {
                        float x = er[lane + 32 * k];
                        acc[0][k] = fmaf(w0, x, acc[0][k]);
                        acc[1][k] = fmaf(w1, x, acc[1][k]);
                        acc[2][k] = fmaf(w2, x, acc[2][k]);
                        acc[3][k] = fmaf(w3, x, acc[3][k]);
                    }
#pragma unroll
                    for (int k = 0; k < 4; k++) {
                        float x = ee[lane + 32 * k];
                        acc[0][4 + k] = fmaf(w0, x, acc[0][4 + k]);
                        acc[1][4 + k] = fmaf(w1, x, acc[1][4 + k]);
                        acc[2][4 + k] = fmaf(w2, x, acc[2][4 + k]);
                        acc[3][4 + k] = fmaf(w3, x, acc[3][4 + k]);
                    }
                }
            }
        }
#pragma unroll
        for (int hh = 0; hh < 4; hh++)
#pragma unroll
            for (int k = 0; k < 8; k++) {
                int f = (k < 4) ? (lane + 32 * k) : (128 + lane + 32 * (k - 4));
                atomicAdd(&ysm[hh * 256 + f], acc[hh][k]);
            }
    }
    __syncthreads();

    // ---- tail: pa = ys @ Wcomb, + es @ WheadT, relu, residual, LayerNorm ----
    {
        int hp = tid >> 7, d = tid & 127;
        float acc = 0.f;
#pragma unroll 1
        for (int hh = 2 * hp; hh < 2 * hp + 2; hh++) {
            const float* wc = g_Wcomb + (size_t)hh * 256 * 128 + d;
            const float* yy = ysm + hh * 256;
            for (int f = 0; f < 256; f++)
                acc = fmaf(yy[f], wc[f * 128], acc);
        }
        pa2[tid] = acc;
    }
    __syncthreads();

    float tval = 0.f;
    if (tid < 128) {
        float pa = pa2[tid] + pa2[128 + tid];
        float ht = 0.f;
        for (int e = 0; e < 128; e++)
            ht = fmaf(es[e], g_WheadT[e * 128 + tid], ht);
        tval = fmaxf(pa + ht, 0.f) + es[tid];
    }

    float v = tval;
#pragma unroll
    for (int off = 16; off; off >>= 1) v += __shfl_xor_sync(0xffffffffu, v, off);
    if (lane == 0) red[w] = v;
    __syncthreads();
    float tot = 0.f;
#pragma unroll
    for (int i = 0; i < NWARP; i++) tot += red[i];
    float mu = tot * (1.f / 128.f);
    __syncthreads();

    float diff = (tid < 128) ? (tval - mu) : 0.f;
    float v2 = diff * diff;
#pragma unroll
    for (int off = 16; off; off >>= 1) v2 += __shfl_xor_sync(0xffffffffu, v2, off);
    if (lane == 0) red[w] = v2;
    __syncthreads();
    float tot2 = 0.f;
#pragma unroll
    for (int i = 0; i < NWARP; i++) tot2 += red[i];
    float var = tot2 * (1.f / 128.f);

    if (tid < 128)
        out[(size_t)sid * 128 + tid] =
            diff * rsqrtf(var + 1e-5f) * lnw[tid] + lnb[tid];
}

// ---------------- launch ----------------
extern "C" void kernel_launch(void* const* d_in, const int* in_sizes, int n_in,
                              void* d_out, int out_size) {
    const int*   ep    = (const int*)d_in[0];
    const int*   lconn = (const int*)d_in[1];
    const int*   rconn = (const int*)d_in[3];
    const float* emb   = (const float*)d_in[5];
    const float* Wv    = (const float*)d_in[6];
    const float* Wk    = (const float*)d_in[7];
    const float* Wq    = (const float*)d_in[8];
    const float* Ww    = (const float*)d_in[9];
    const float* Whead = (const float*)d_in[10];
    const float* lnw   = (const float*)d_in[11];
    const float* lnb   = (const float*)d_in[12];
    float* out = (float*)d_out;

    const int B = in_sizes[0] / 2;          // 1024
    const int SIDES = 2 * B;                // 2048

    static bool attr_done = false;
    if (!attr_done) {
        cudaFuncSetAttribute(mega, cudaFuncAttributeMaxDynamicSharedMemorySize, SM_TOT);
        attr_done = true;
    }

    prep_wcomb<<<dim3(256, 4), 128>>>(Wv, Ww);
    prep_wheadT<<<128, 128>>>(Whead);
    prep_embF<<<(int)(((size_t)VP1 * 128 / 16 + 255) / 256), 256>>>(emb);
    prep_wfragF<<<dim3(8, 8), 32>>>(Wk, Wq);

    mega<<<SIDES, NTHR, SM_TOT>>>(ep, lconn, rconn, emb, lnw, lnb, out);
}

// round 12
// speedup vs baseline: 1.1266x; 1.1266x over previous
#include <cuda_runtime.h>
#include <cuda_bf16.h>
#include <cuda_fp8.h>
#include <math.h>
#include <stdint.h>

#define NN 200
#define DD 128
#define PAD_IDX 100000
#define VP1 100001
#define NTHR 512
#define NWARP 16

// ---------------- device scratch (no runtime allocation allowed) ----------------
__device__ unsigned char g_embF[(size_t)VP1 * 128];   // fp8 e4m3 embeddings x16 (12.8 MB)
__device__ uint2 g_WfragF[8 * 8 * 16 * 32];           // fp8 B fragments (256 KB)
__device__ float g_Wcomb[4 * 256 * 128];              // [h][f][d] Wv folded with Ww
__device__ float g_WheadT[128 * 128];                 // [e][d] Whead transposed

// ================= helpers =================
__device__ __forceinline__ uint32_t smem_u32(const void* p) {
    uint32_t a;
    asm("{ .reg .u64 t; cvta.to.shared.u64 t, %1; cvt.u32.u64 %0, t; }" : "=r"(a) : "l"(p));
    return a;
}
__device__ __forceinline__ void ldsm_x4(uint32_t* r, uint32_t a) {
    asm volatile("ldmatrix.sync.aligned.m8n8.x4.shared.b16 {%0,%1,%2,%3}, [%4];"
                 : "=r"(r[0]), "=r"(r[1]), "=r"(r[2]), "=r"(r[3]) : "r"(a));
}
__device__ __forceinline__ void ldsm_x2(uint32_t* r, uint32_t a) {
    asm volatile("ldmatrix.sync.aligned.m8n8.x2.shared.b16 {%0,%1}, [%2];"
                 : "=r"(r[0]), "=r"(r[1]) : "r"(a));
}
__device__ __forceinline__ void mma_fp8(float* c, const uint32_t* a, uint32_t b0, uint32_t b1) {
    asm volatile("mma.sync.aligned.m16n8k32.row.col.f32.e4m3.e4m3.f32 "
                 "{%0,%1,%2,%3}, {%4,%5,%6,%7}, {%8,%9}, {%0,%1,%2,%3};"
                 : "+f"(c[0]), "+f"(c[1]), "+f"(c[2]), "+f"(c[3])
                 : "r"(a[0]), "r"(a[1]), "r"(a[2]), "r"(a[3]), "r"(b0), "r"(b1));
}
__device__ __forceinline__ unsigned short fp8x2(float lo, float hi) {
    return (unsigned short)__nv_cvt_float2_to_fp8x2(make_float2(lo, hi),
                                                    __NV_SATFINITE, __NV_E4M3);
}
__device__ __forceinline__ uint4 pack16_fp8_x16(float4 v0, float4 v1, float4 v2, float4 v3) {
    uint4 o;
    o.x = (uint32_t)fp8x2(v0.x * 16.f, v0.y * 16.f) | ((uint32_t)fp8x2(v0.z * 16.f, v0.w * 16.f) << 16);
    o.y = (uint32_t)fp8x2(v1.x * 16.f, v1.y * 16.f) | ((uint32_t)fp8x2(v1.z * 16.f, v1.w * 16.f) << 16);
    o.z = (uint32_t)fp8x2(v2.x * 16.f, v2.y * 16.f) | ((uint32_t)fp8x2(v2.z * 16.f, v2.w * 16.f) << 16);
    o.w = (uint32_t)fp8x2(v3.x * 16.f, v3.y * 16.f) | ((uint32_t)fp8x2(v3.z * 16.f, v3.w * 16.f) << 16);
    return o;
}

// ---------------- ONE fused prep kernel (so launch #odd = mega for ncu) ------
// blocks [0,3126)      : embF  (fp8 conversion of emb, x16)
// blocks [3126,4150)   : wcomb (Wv folded with Ww)
// blocks [4150,4214)   : wheadT
// blocks [4214,4278)   : wfragF (ldmatrix-shuffled fp8 W fragments)
#define PREP_GRID 4278
__global__ void __launch_bounds__(256)
prep_all(const float* __restrict__ emb, const float* __restrict__ Wv,
         const float* __restrict__ Ww, const float* __restrict__ Whead,
         const float* __restrict__ Wk, const float* __restrict__ Wq) {
    __shared__ unsigned char Wsh[128 * 48];
    int blk = blockIdx.x, tid = threadIdx.x;

    if (blk < 3126) {
        size_t i = ((size_t)blk * 256 + tid) * 16;
        if (i < (size_t)VP1 * 128) {
            const float4* s = reinterpret_cast<const float4*>(emb + i);
            *reinterpret_cast<uint4*>(g_embF + i) = pack16_fp8_x16(s[0], s[1], s[2], s[3]);
        }
    } else if (blk < 4150) {
        int j = blk - 3126;              // [0,1024): f = j%256, h = j/256
        int f = j & 255, h = j >> 8;
        if (tid < 128) {
            float a = 0.f;
            for (int d = 0; d < 128; d++)
                a = fmaf(Wv[(h * 128 + d) * 256 + f], Ww[tid * 512 + h * 128 + d], a);
            g_Wcomb[(h * 256 + f) * 128 + tid] = a;
        }
    } else if (blk < 4214) {
        int idx = (blk - 4150) * 256 + tid;   // [0,16384)
        int e = idx >> 7, d = idx & 127;
        g_WheadT[e * 128 + d] = Whead[d * 128 + e];
    } else {
        int j = blk - 4214;              // [0,64): t = j/8, ks = j%8
        int t = j >> 3, ks = j & 7;
        if (tid < 32) {
            int lane = tid;
            const float* Wsrc = ((t < 4) ? Wk : Wq) + (size_t)(t & 3) * 128 * 256;
            for (int i = lane; i < 256; i += 32) {
                int rn = i >> 1, half = i & 1;
                const float4* s = reinterpret_cast<const float4*>(Wsrc + rn * 256 + ks * 32 + half * 16);
                *reinterpret_cast<uint4*>(&Wsh[rn * 48 + half * 16]) =
                    pack16_fp8_x16(s[0], s[1], s[2], s[3]);
            }
            __syncwarp();
            uint32_t base = smem_u32(Wsh) + (uint32_t)((lane & 7) * 48 + ((lane >> 3) & 1) * 16);
            for (int f = 0; f < 16; f++) {
                uint32_t bb[2];
                ldsm_x2(bb, base + f * (8 * 48));
                g_WfragF[((t * 8 + ks) * 16 + f) * 32 + lane] = make_uint2(bb[0], bb[1]);
            }
        }
    }
}

// ---------------- the fused mega-kernel (fp8, 512 thr, split-half attn) ------
// 16 warps. proj: 26 jobs (kq,mt). attn: 26 jobs (mt,half) with c[13][4]
// (52 regs -> fits the 128-reg/512-thread ceiling), softmax WITHOUT the
// row-max pass (|s|~1e-3; masked entries hard 0/1; fully-masked rows
// reproduce the reference's uniform 1/200), row sums via smem Zr with a
// uniform 2-iteration barrier schedule (pairs (2mt,2mt+1) share an iter).
#define XSB 272
#define KQB 144
#define OFF_X    0
#define OFF_K    56576
#define OFF_Q    86528
#define OFF_WS4  116480
#define OFF_ZR   119680
#define OFF_MSK  123008
#define OFF_YS   123840
#define OFF_ES   127936
#define OFF_PA4  128448
#define OFF_RED  130496
#define OFF_IDX  130560
#define SM_TOT   132160

__global__ void __launch_bounds__(NTHR, 1)
mega(const int* __restrict__ ep, const int* __restrict__ lconn,
     const int* __restrict__ rconn, const float* __restrict__ emb,
     const float* __restrict__ lnw, const float* __restrict__ lnb,
     float* __restrict__ out) {
    extern __shared__ char smem[];
    uint32_t sb = smem_u32(smem);
    float* ws4 = reinterpret_cast<float*>(smem + OFF_WS4);   // [4][200]
    float* Zr  = reinterpret_cast<float*>(smem + OFF_ZR);    // [4][208]
    float* msk = reinterpret_cast<float*>(smem + OFF_MSK);
    float* ysm = reinterpret_cast<float*>(smem + OFF_YS);    // [4][256]
    float* es  = reinterpret_cast<float*>(smem + OFF_ES);
    float* pa4 = reinterpret_cast<float*>(smem + OFF_PA4);   // [512]
    float* red = reinterpret_cast<float*>(smem + OFF_RED);
    int*   reli = reinterpret_cast<int*>(smem + OFF_IDX);
    int*   enti = reli + 200;

    int tid = threadIdx.x, w = tid >> 5, lane = tid & 31;
    int sid = blockIdx.x, b = sid >> 1;
    const int* conn = (sid & 1) ? rconn : lconn;

    // gather X fp8 (rows >= 200 zeroed)
    for (int i = tid; i < 208 * 16; i += NTHR) {
        int n = i >> 4, q = i & 15;
        uint4 v = make_uint4(0u, 0u, 0u, 0u);
        if (n < 200) {
            int idx = conn[(b * NN + n) * 2 + (q >> 3)];
            v = *reinterpret_cast<const uint4*>(g_embF + (size_t)idx * 128 + (q & 7) * 16);
        }
        *reinterpret_cast<uint4*>(smem + OFF_X + n * XSB + q * 16) = v;
    }
    for (int i = tid; i < 208; i += NTHR) {
        if (i < 200) {
            int2 cc = reinterpret_cast<const int2*>(conn)[b * NN + i];
            reli[i] = cc.x; enti[i] = cc.y;
            msk[i] = (cc.x == PAD_IDX) ? 1.f : 0.f;
        } else {
            msk[i] = 1.f;
        }
    }
    for (int i = tid; i < 800; i += NTHR) ws4[i] = 0.f;
    for (int i = tid; i < 832; i += NTHR) Zr[i] = 0.f;
    for (int i = tid; i < 1024; i += NTHR) ysm[i] = 0.f;
    if (tid < 128) es[tid] = emb[(size_t)ep[b * 2 + (sid & 1)] * DD + tid];
    __syncthreads();

    uint32_t qbb = sb + OFF_Q + (uint32_t)((lane & 7) * KQB + ((lane >> 3) & 1) * 16);
    int d0 = (lane & 3) * 2;
    int mc = (lane & 3) * 2;
    // emb,W scaled x16 each -> S_mma = 65536 * S_true
    const float scale = 0.08838834764831845f / 65536.0f;

    for (int h = 0; h < 4; h++) {
        // ---- project K_h and Q_h into SMEM fp8: 26 jobs (kq, mt) ----
#pragma unroll 1
        for (int j = w; j < 26; j += NWARP) {
            int kq = j / 13, mt = j % 13;
            const uint2* wf = g_WfragF + (size_t)(kq * 4 + h) * 4096 + lane;
            char* dst = smem + (kq ? OFF_Q : OFF_K);
            uint32_t xa = sb + OFF_X +
                (uint32_t)((mt * 16 + (lane & 15)) * XSB + (lane >> 4) * 16);
            int r0 = mt * 16 + (lane >> 2);
            float c[16][4];
#pragma unroll
            for (int f = 0; f < 16; f++) { c[f][0] = 0.f; c[f][1] = 0.f; c[f][2] = 0.f; c[f][3] = 0.f; }
#pragma unroll 1
            for (int ks = 0; ks < 8; ks++) {
                uint32_t a[4];
                ldsm_x4(a, xa + ks * 32);
                const uint2* wfk = wf + ks * 512;
#pragma unroll
                for (int f = 0; f < 16; f++) {
                    uint2 bv = __ldg(wfk + f * 32);
                    mma_fp8(c[f], a, bv.x, bv.y);
                }
            }
#pragma unroll
            for (int f = 0; f < 16; f++) {
                *reinterpret_cast<unsigned short*>(dst + r0 * KQB + f * 8 + d0) =
                    fp8x2(c[f][0], c[f][1]);
                *reinterpret_cast<unsigned short*>(dst + (r0 + 8) * KQB + f * 8 + d0) =
                    fp8x2(c[f][2], c[f][3]);
            }
        }
        __syncthreads();

        // ---- attention: 26 jobs (mt, half); 2 uniform iterations ----
        float* wsh = ws4 + h * 200;
        float* zrh = Zr + h * 208;
#pragma unroll 1
        for (int it = 0; it < 2; it++) {
            int j = w + it * NWARP;
            bool act = (j < 26);
            int mt = act ? (j >> 1) : 0;
            int half = act ? (j & 1) : 0;
            int n0 = mt * 16 + (lane >> 2);
            float c[13][4];
            if (act) {
#pragma unroll
                for (int f = 0; f < 13; f++) { c[f][0] = 0.f; c[f][1] = 0.f; c[f][2] = 0.f; c[f][3] = 0.f; }
                uint32_t ka = sb + OFF_K +
                    (uint32_t)((mt * 16 + (lane & 15)) * KQB + (lane >> 4) * 16);
                uint32_t qh = qbb + (uint32_t)(half * 13) * (8 * KQB);
#pragma unroll 1
                for (int ks = 0; ks < 4; ks++) {
                    uint32_t a[4];
                    ldsm_x4(a, ka + ks * 32);
#pragma unroll
                    for (int f = 0; f < 13; f++) {
                        uint32_t bb[2];
                        ldsm_x2(bb, qh + f * (8 * KQB) + ks * 32);
                        mma_fp8(c[f], a, bb[0], bb[1]);
                    }
                }
                // e-values (no row-max; masked entries 0/1)
#pragma unroll
                for (int p = 0; p < 2; p++) {
                    float rm = msk[n0 + p * 8];
#pragma unroll
                    for (int f = 0; f < 13; f++) {
#pragma unroll
                        for (int jj = 0; jj < 2; jj++) {
                            int m = (half * 13 + f) * 8 + mc + jj;
                            float e;
                            if (m >= 200)            e = 0.f;
                            else if (rm > 0.5f)      e = 1.f;     // fully-masked row -> uniform
                            else if (msk[m] > 0.5f)  e = 0.f;
                            else                     e = __expf(c[f][2 * p + jj] * scale);
                            c[f][2 * p + jj] = e;
                        }
                    }
                }
                // partial row sums -> Zr
                float z0 = 0.f, z1 = 0.f;
#pragma unroll
                for (int f = 0; f < 13; f++) {
                    z0 += c[f][0] + c[f][1];
                    z1 += c[f][2] + c[f][3];
                }
                z0 += __shfl_xor_sync(0xffffffffu, z0, 1);
                z0 += __shfl_xor_sync(0xffffffffu, z0, 2);
                z1 += __shfl_xor_sync(0xffffffffu, z1, 1);
                z1 += __shfl_xor_sync(0xffffffffu, z1, 2);
                if ((lane & 3) == 0) {
                    atomicAdd(zrh + n0, z0);
                    atomicAdd(zrh + n0 + 8, z1);
                }
            }
            __syncthreads();   // uniform across warps; Zr complete for this it's rows
            if (act) {
                float inv0 = (n0 < 200)     ? (1.f / zrh[n0])     : 0.f;
                float inv1 = (n0 + 8 < 200) ? (1.f / zrh[n0 + 8]) : 0.f;
#pragma unroll
                for (int f = 0; f < 13; f++) {
#pragma unroll
                    for (int jj = 0; jj < 2; jj++) {
                        float v = c[f][jj] * inv0 + c[f][2 + jj] * inv1;
                        v += __shfl_xor_sync(0xffffffffu, v, 4);
                        v += __shfl_xor_sync(0xffffffffu, v, 8);
                        v += __shfl_xor_sync(0xffffffffu, v, 16);
                        if ((lane >> 2) == 0) {
                            int m = (half * 13 + f) * 8 + mc + jj;
                            if (m < 200) atomicAdd(wsh + m, v);
                        }
                    }
                }
            }
        }
        __syncthreads();   // K/Q safe to overwrite; ws4[h] complete
    }

    // ---- single y pass: each emb row loaded ONCE, 4 head weights fused ----
    {
        float acc[4][8];
#pragma unroll
        for (int hh = 0; hh < 4; hh++)
#pragma unroll
            for (int k = 0; k < 8; k++) acc[hh][k] = 0.f;
#pragma unroll 1
        for (int mt = w; mt < 13; mt += NWARP) {
            int m0 = mt * 16;
            for (int i = 0; i < 16; i++) {
                int m = m0 + i;
                if (m < 200) {
                    float w0 = ws4[m], w1 = ws4[200 + m], w2 = ws4[400 + m], w3 = ws4[600 + m];
                    const float* er = emb + (size_t)reli[m] * DD;
                    const float* ee = emb + (size_t)enti[m] * DD;
#pragma unroll
                    for (int k = 0; k < 4; k++) {
                        float x = er[lane + 32 * k];
                        acc[0][k] = fmaf(w0, x, acc[0][k]);
                        acc[1][k] = fmaf(w1, x, acc[1][k]);
                        acc[2][k] = fmaf(w2, x, acc[2][k]);
                        acc[3][k] = fmaf(w3, x, acc[3][k]);
                    }
#pragma unroll
                    for (int k = 0; k < 4; k++) {
                        float x = ee[lane + 32 * k];
                        acc[0][4 + k] = fmaf(w0, x, acc[0][4 + k]);
                        acc[1][4 + k] = fmaf(w1, x, acc[1][4 + k]);
                        acc[2][4 + k] = fmaf(w2, x, acc[2][4 + k]);
                        acc[3][4 + k] = fmaf(w3, x, acc[3][4 + k]);
                    }
                }
            }
        }
        if (w < 13) {
#pragma unroll
            for (int hh = 0; hh < 4; hh++)
#pragma unroll
                for (int k = 0; k < 8; k++) {
                    int f = (k < 4) ? (lane + 32 * k) : (128 + lane + 32 * (k - 4));
                    atomicAdd(&ysm[hh * 256 + f], acc[hh][k]);
                }
        }
    }
    __syncthreads();

    // ---- tail: pa = ys @ Wcomb (4-way parallel), + es @ WheadT, relu, LN ----
    {
        int hp = tid >> 7, d = tid & 127;
        const float* wc = g_Wcomb + (size_t)hp * 256 * 128 + d;
        const float* yy = ysm + hp * 256;
        float acc = 0.f;
        for (int f = 0; f < 256; f++)
            acc = fmaf(yy[f], wc[f * 128], acc);
        pa4[tid] = acc;
    }
    __syncthreads();

    float tval = 0.f;
    if (tid < 128) {
        float pa = pa4[tid] + pa4[128 + tid] + pa4[256 + tid] + pa4[384 + tid];
        float ht = 0.f;
        for (int e = 0; e < 128; e++)
            ht = fmaf(es[e], g_WheadT[e * 128 + tid], ht);
        tval = fmaxf(pa + ht, 0.f) + es[tid];
    }

    float v = tval;
#pragma unroll
    for (int off = 16; off; off >>= 1) v += __shfl_xor_sync(0xffffffffu, v, off);
    if (lane == 0) red[w] = v;
    __syncthreads();
    float tot = 0.f;
#pragma unroll
    for (int i = 0; i < NWARP; i++) tot += red[i];
    float mu = tot * (1.f / 128.f);
    __syncthreads();

    float diff = (tid < 128) ? (tval - mu) : 0.f;
    float v2 = diff * diff;
#pragma unroll
    for (int off = 16; off; off >>= 1) v2 += __shfl_xor_sync(0xffffffffu, v2, off);
    if (lane == 0) red[w] = v2;
    __syncthreads();
    float tot2 = 0.f;
#pragma unroll
    for (int i = 0; i < NWARP; i++) tot2 += red[i];
    float var = tot2 * (1.f / 128.f);

    if (tid < 128)
        out[(size_t)sid * 128 + tid] =
            diff * rsqrtf(var + 1e-5f) * lnw[tid] + lnb[tid];
}

// ---------------- launch ----------------
extern "C" void kernel_launch(void* const* d_in, const int* in_sizes, int n_in,
                              void* d_out, int out_size) {
    const int*   ep    = (const int*)d_in[0];
    const int*   lconn = (const int*)d_in[1];
    const int*   rconn = (const int*)d_in[3];
    const float* emb   = (const float*)d_in[5];
    const float* Wv    = (const float*)d_in[6];
    const float* Wk    = (const float*)d_in[7];
    const float* Wq    = (const float*)d_in[8];
    const float* Ww    = (const float*)d_in[9];
    const float* Whead = (const float*)d_in[10];
    const float* lnw   = (const float*)d_in[11];
    const float* lnb   = (const float*)d_in[12];
    float* out = (float*)d_out;

    const int B = in_sizes[0] / 2;          // 1024
    const int SIDES = 2 * B;                // 2048

    static bool attr_done = false;
    if (!attr_done) {
        cudaFuncSetAttribute(mega, cudaFuncAttributeMaxDynamicSharedMemorySize, SM_TOT);
        attr_done = true;
    }

    prep_all<<<PREP_GRID, 256>>>(emb, Wv, Ww, Whead, Wk, Wq);
    mega<<<SIDES, NTHR, SM_TOT>>>(ep, lconn, rconn, emb, lnw, lnb, out);
}

// round 13
// speedup vs baseline: 1.2956x; 1.1500x over previous
#include <cuda_runtime.h>
#include <cuda_bf16.h>
#include <cuda_fp8.h>
#include <math.h>
#include <stdint.h>

#define NN 200
#define DD 128
#define PAD_IDX 100000
#define VP1 100001
#define NTHR 416
#define NWARP 13

// ---------------- device scratch (no runtime allocation allowed) ----------------
__device__ unsigned char g_embF[(size_t)VP1 * 128];   // fp8 e4m3 embeddings x16 (12.8 MB)
__device__ uint4 g_Wfrag2[8 * 8 * 8 * 32];            // paired fp8 B fragments (256 KB)
__device__ float g_Wcomb[4 * 256 * 128];              // [h][f][d] Wv folded with Ww
__device__ float g_WheadT[128 * 128];                 // [e][d] Whead transposed

// ================= helpers =================
__device__ __forceinline__ uint32_t smem_u32(const void* p) {
    uint32_t a;
    asm("{ .reg .u64 t; cvta.to.shared.u64 t, %1; cvt.u32.u64 %0, t; }" : "=r"(a) : "l"(p));
    return a;
}
__device__ __forceinline__ void ldsm_x4(uint32_t* r, uint32_t a) {
    asm volatile("ldmatrix.sync.aligned.m8n8.x4.shared.b16 {%0,%1,%2,%3}, [%4];"
                 : "=r"(r[0]), "=r"(r[1]), "=r"(r[2]), "=r"(r[3]) : "r"(a));
}
__device__ __forceinline__ void ldsm_x2(uint32_t* r, uint32_t a) {
    asm volatile("ldmatrix.sync.aligned.m8n8.x2.shared.b16 {%0,%1}, [%2];"
                 : "=r"(r[0]), "=r"(r[1]) : "r"(a));
}
__device__ __forceinline__ void mma_fp8(float* c, const uint32_t* a, uint32_t b0, uint32_t b1) {
    asm volatile("mma.sync.aligned.m16n8k32.row.col.f32.e4m3.e4m3.f32 "
                 "{%0,%1,%2,%3}, {%4,%5,%6,%7}, {%8,%9}, {%0,%1,%2,%3};"
                 : "+f"(c[0]), "+f"(c[1]), "+f"(c[2]), "+f"(c[3])
                 : "r"(a[0]), "r"(a[1]), "r"(a[2]), "r"(a[3]), "r"(b0), "r"(b1));
}
__device__ __forceinline__ unsigned short fp8x2(float lo, float hi) {
    return (unsigned short)__nv_cvt_float2_to_fp8x2(make_float2(lo, hi),
                                                    __NV_SATFINITE, __NV_E4M3);
}
__device__ __forceinline__ uint4 pack16_fp8_x16(float4 v0, float4 v1, float4 v2, float4 v3) {
    uint4 o;
    o.x = (uint32_t)fp8x2(v0.x * 16.f, v0.y * 16.f) | ((uint32_t)fp8x2(v0.z * 16.f, v0.w * 16.f) << 16);
    o.y = (uint32_t)fp8x2(v1.x * 16.f, v1.y * 16.f) | ((uint32_t)fp8x2(v1.z * 16.f, v1.w * 16.f) << 16);
    o.z = (uint32_t)fp8x2(v2.x * 16.f, v2.y * 16.f) | ((uint32_t)fp8x2(v2.z * 16.f, v2.w * 16.f) << 16);
    o.w = (uint32_t)fp8x2(v3.x * 16.f, v3.y * 16.f) | ((uint32_t)fp8x2(v3.z * 16.f, v3.w * 16.f) << 16);
    return o;
}

// ---------------- ONE fused prep kernel (keeps mega at launch parity for ncu) --
// blocks [0,3126)    : embF
// blocks [3126,4150) : wcomb
// blocks [4150,4214) : wheadT
// blocks [4214,4278) : wfrag2 (ldmatrix-shuffled fp8 W fragments, PAIRED uint4)
#define PREP_GRID 4278
__global__ void __launch_bounds__(256)
prep_all(const float* __restrict__ emb, const float* __restrict__ Wv,
         const float* __restrict__ Ww, const float* __restrict__ Whead,
         const float* __restrict__ Wk, const float* __restrict__ Wq) {
    __shared__ unsigned char Wsh[128 * 48];
    int blk = blockIdx.x, tid = threadIdx.x;

    if (blk < 3126) {
        size_t i = ((size_t)blk * 256 + tid) * 16;
        if (i < (size_t)VP1 * 128) {
            const float4* s = reinterpret_cast<const float4*>(emb + i);
            *reinterpret_cast<uint4*>(g_embF + i) = pack16_fp8_x16(s[0], s[1], s[2], s[3]);
        }
    } else if (blk < 4150) {
        int j = blk - 3126;
        int f = j & 255, h = j >> 8;
        if (tid < 128) {
            float a = 0.f;
            for (int d = 0; d < 128; d++)
                a = fmaf(Wv[(h * 128 + d) * 256 + f], Ww[tid * 512 + h * 128 + d], a);
            g_Wcomb[(h * 256 + f) * 128 + tid] = a;
        }
    } else if (blk < 4214) {
        int idx = (blk - 4150) * 256 + tid;
        int e = idx >> 7, d = idx & 127;
        g_WheadT[e * 128 + d] = Whead[d * 128 + e];
    } else {
        int j = blk - 4214;              // [0,64): t = j/8, ks = j%8
        int t = j >> 3, ks = j & 7;
        if (tid < 32) {
            int lane = tid;
            const float* Wsrc = ((t < 4) ? Wk : Wq) + (size_t)(t & 3) * 128 * 256;
            for (int i = lane; i < 256; i += 32) {
                int rn = i >> 1, half = i & 1;
                const float4* s = reinterpret_cast<const float4*>(Wsrc + rn * 256 + ks * 32 + half * 16);
                *reinterpret_cast<uint4*>(&Wsh[rn * 48 + half * 16]) =
                    pack16_fp8_x16(s[0], s[1], s[2], s[3]);
            }
            __syncwarp();
            uint32_t base = smem_u32(Wsh) + (uint32_t)((lane & 7) * 48 + ((lane >> 3) & 1) * 16);
            uint32_t pv0 = 0, pv1 = 0;
            for (int f = 0; f < 16; f++) {
                uint32_t bb[2];
                ldsm_x2(bb, base + f * (8 * 48));
                if (f & 1) {
                    g_Wfrag2[((t * 8 + ks) * 8 + (f >> 1)) * 32 + lane] =
                        make_uint4(pv0, pv1, bb[0], bb[1]);
                } else {
                    pv0 = bb[0]; pv1 = bb[1];
                }
            }
        }
    }
}

// ---------------- the fused mega-kernel (fp8, 416 thr, lean inner loops) ------
// 13 warps, R10-proven phase structure. Per head: proj K,Q (paired-uint4 W
// frags, 8 LDG.128/ks), attn with ldsm.x4 B (2 n-blocks per ldsm) and
// no-row-max softmax (scores ~1e-3; masked entries hard 0/1; proven R12).
#define XSB 272
#define KQB 144
#define OFF_X   0
#define OFF_K   56576
#define OFF_Q   86528
#define OFF_WS4 116480
#define OFF_MSK 119680
#define OFF_YS  120512
#define OFF_ES  124608
#define OFF_PA2 125120
#define OFF_RED 126144
#define OFF_IDX 126208
#define SM_TOT  127808

__global__ void __launch_bounds__(NTHR, 1)
mega(const int* __restrict__ ep, const int* __restrict__ lconn,
     const int* __restrict__ rconn, const float* __restrict__ emb,
     const float* __restrict__ lnw, const float* __restrict__ lnb,
     float* __restrict__ out) {
    extern __shared__ char smem[];
    uint32_t sb = smem_u32(smem);
    float* ws4 = reinterpret_cast<float*>(smem + OFF_WS4);   // [4][200]
    float* msk = reinterpret_cast<float*>(smem + OFF_MSK);
    float* ysm = reinterpret_cast<float*>(smem + OFF_YS);    // [4][256]
    float* es  = reinterpret_cast<float*>(smem + OFF_ES);
    float* pa2 = reinterpret_cast<float*>(smem + OFF_PA2);
    float* red = reinterpret_cast<float*>(smem + OFF_RED);
    int*   reli = reinterpret_cast<int*>(smem + OFF_IDX);
    int*   enti = reli + 200;

    int tid = threadIdx.x, w = tid >> 5, lane = tid & 31;
    int sid = blockIdx.x, b = sid >> 1;
    const int* conn = (sid & 1) ? rconn : lconn;

    // gather X fp8 (rows >= 200 zeroed)
    for (int i = tid; i < 208 * 16; i += NTHR) {
        int n = i >> 4, q = i & 15;
        uint4 v = make_uint4(0u, 0u, 0u, 0u);
        if (n < 200) {
            int idx = conn[(b * NN + n) * 2 + (q >> 3)];
            v = *reinterpret_cast<const uint4*>(g_embF + (size_t)idx * 128 + (q & 7) * 16);
        }
        *reinterpret_cast<uint4*>(smem + OFF_X + n * XSB + q * 16) = v;
    }
    for (int i = tid; i < 208; i += NTHR) {
        if (i < 200) {
            int2 cc = reinterpret_cast<const int2*>(conn)[b * NN + i];
            reli[i] = cc.x; enti[i] = cc.y;
            msk[i] = (cc.x == PAD_IDX) ? 1.f : 0.f;
        } else {
            msk[i] = 1.f;
        }
    }
    for (int i = tid; i < 800; i += NTHR) ws4[i] = 0.f;
    for (int i = tid; i < 1024; i += NTHR) ysm[i] = 0.f;
    if (tid < 128) es[tid] = emb[(size_t)ep[b * 2 + (sid & 1)] * DD + tid];
    __syncthreads();

    // per-warp addresses
    uint32_t xa = sb + OFF_X + (uint32_t)((w * 16 + (lane & 15)) * XSB + (lane >> 4) * 16);
    uint32_t ka = sb + OFF_K + (uint32_t)((w * 16 + (lane & 15)) * KQB + (lane >> 4) * 16);
    // x4 B address: lanes 0-15 -> rows +0 (k-lo/k-hi), lanes 16-31 -> rows +8
    uint32_t qb4 = sb + OFF_Q +
        (uint32_t)(((lane & 7) + 8 * ((lane >> 4) & 1)) * KQB + ((lane >> 3) & 1) * 16);
    int r0 = w * 16 + (lane >> 2);
    int d0 = (lane & 3) * 2;
    // emb,W scaled x16 each -> S_mma = 65536 * S_true
    const float scale = 0.08838834764831845f / 65536.0f;

    for (int h = 0; h < 4; h++) {
        // ---- project K_h (kq=0) and Q_h (kq=1) into SMEM fp8 ----
#pragma unroll 1
        for (int kq = 0; kq < 2; kq++) {
            int t = kq * 4 + h;
            const uint4* wf = g_Wfrag2 + (size_t)t * 2048 + lane;
            char* dst = smem + (kq ? OFF_Q : OFF_K);
            float c[16][4];
#pragma unroll
            for (int f = 0; f < 16; f++) { c[f][0] = 0.f; c[f][1] = 0.f; c[f][2] = 0.f; c[f][3] = 0.f; }
#pragma unroll 1
            for (int ks = 0; ks < 8; ks++) {
                uint32_t a[4];
                ldsm_x4(a, xa + ks * 32);
                const uint4* wk2 = wf + ks * 256;
#pragma unroll
                for (int fp = 0; fp < 8; fp++) {
                    uint4 v = __ldg(wk2 + fp * 32);
                    mma_fp8(c[2 * fp],     a, v.x, v.y);
                    mma_fp8(c[2 * fp + 1], a, v.z, v.w);
                }
            }
#pragma unroll
            for (int f = 0; f < 16; f++) {
                *reinterpret_cast<unsigned short*>(dst + r0 * KQB + f * 8 + d0) =
                    fp8x2(c[f][0], c[f][1]);
                *reinterpret_cast<unsigned short*>(dst + (r0 + 8) * KQB + f * 8 + d0) =
                    fp8x2(c[f][2], c[f][3]);
            }
        }
        __syncthreads();

        // ---- attention: scores, mask, no-max softmax, column sums -> ws4[h] ----
        {
            float c[26][4];
#pragma unroll
            for (int f = 0; f < 26; f++) { c[f][0] = 0.f; c[f][1] = 0.f; c[f][2] = 0.f; c[f][3] = 0.f; }
#pragma unroll 1
            for (int ks = 0; ks < 4; ks++) {
                uint32_t a[4];
                ldsm_x4(a, ka + ks * 32);
#pragma unroll
                for (int fp = 0; fp < 13; fp++) {
                    uint32_t bb[4];
                    ldsm_x4(bb, qb4 + (uint32_t)(fp * 16) * KQB + ks * 32);
                    mma_fp8(c[2 * fp],     a, bb[0], bb[1]);
                    mma_fp8(c[2 * fp + 1], a, bb[2], bb[3]);
                }
            }
            int n0 = w * 16 + (lane >> 2);
            int mc = (lane & 3) * 2;
#pragma unroll
            for (int p = 0; p < 2; p++) {
                int nn = n0 + p * 8;
                float rm = msk[nn];
                float Z = 0.f;
#pragma unroll
                for (int f = 0; f < 26; f++) {
#pragma unroll
                    for (int j = 0; j < 2; j++) {
                        int m = f * 8 + mc + j;
                        float e;
                        if (m >= 200)            e = 0.f;
                        else if (rm > 0.5f)      e = 1.f;   // fully-masked row -> uniform
                        else if (msk[m] > 0.5f)  e = 0.f;
                        else                     e = __expf(c[f][2 * p + j] * scale);
                        c[f][2 * p + j] = e;
                        Z += e;
                    }
                }
                Z += __shfl_xor_sync(0xffffffffu, Z, 1);
                Z += __shfl_xor_sync(0xffffffffu, Z, 2);
                float inv = (nn < 200) ? (1.f / Z) : 0.f;
#pragma unroll
                for (int f = 0; f < 26; f++) {
                    c[f][2 * p + 0] *= inv;
                    c[f][2 * p + 1] *= inv;
                }
            }
            float* wsh = ws4 + h * 200;
#pragma unroll
            for (int f = 0; f < 26; f++) {
#pragma unroll
                for (int j = 0; j < 2; j++) {
                    float v = c[f][j] + c[f][2 + j];
                    v += __shfl_xor_sync(0xffffffffu, v, 4);
                    v += __shfl_xor_sync(0xffffffffu, v, 8);
                    v += __shfl_xor_sync(0xffffffffu, v, 16);
                    if ((lane >> 2) == 0) {
                        int m = f * 8 + mc + j;
                        if (m < 200) atomicAdd(wsh + m, v);
                    }
                }
            }
        }
        __syncthreads();   // K/Q safe to overwrite; ws4[h] complete
    }

    // ---- single y pass: each emb row loaded ONCE, 4 head weights fused ----
    {
        float acc[4][8];
#pragma unroll
        for (int hh = 0; hh < 4; hh++)
#pragma unroll
            for (int k = 0; k < 8; k++) acc[hh][k] = 0.f;
        int m0 = w * 16;
        for (int i = 0; i < 16; i++) {
            int m = m0 + i;
            if (m < 200) {
                float w0 = ws4[m], w1 = ws4[200 + m], w2 = ws4[400 + m], w3 = ws4[600 + m];
                const float* er = emb + (size_t)reli[m] * DD;
                const float* ee = emb + (size_t)enti[m] * DD;
#pragma unroll
                for (int k = 0; k < 4; k++) {
                    float x = er[lane + 32 * k];
                    acc[0][k] = fmaf(w0, x, acc[0][k]);
                    acc[1][k] = fmaf(w1, x, acc[1][k]);
                    acc[2][k] = fmaf(w2, x, acc[2][k]);
                    acc[3][k] = fmaf(w3, x, acc[3][k]);
                }
#pragma unroll
                for (int k = 0; k < 4; k++) {
                    float x = ee[lane + 32 * k];
                    acc[0][4 + k] = fmaf(w0, x, acc[0][4 + k]);
                    acc[1][4 + k] = fmaf(w1, x, acc[1][4 + k]);
                    acc[2][4 + k] = fmaf(w2, x, acc[2][4 + k]);
                    acc[3][4 + k] = fmaf(w3, x, acc[3][4 + k]);
                }
            }
        }
#pragma unroll
        for (int hh = 0; hh < 4; hh++)
#pragma unroll
            for (int k = 0; k < 8; k++) {
                int f = (k < 4) ? (lane + 32 * k) : (128 + lane + 32 * (k - 4));
                atomicAdd(&ysm[hh * 256 + f], acc[hh][k]);
            }
    }
    __syncthreads();

    // ---- tail: pa = ys @ Wcomb, + es @ WheadT, relu, residual, LayerNorm ----
    if (tid < 256) {
        int hp = tid >> 7, d = tid & 127;
        float acc = 0.f;
#pragma unroll 1
        for (int hh = 2 * hp; hh < 2 * hp + 2; hh++) {
            const float* wc = g_Wcomb + (size_t)hh * 256 * 128 + d;
            const float* yy = ysm + hh * 256;
            for (int f = 0; f < 256; f++)
                acc = fmaf(yy[f], wc[f * 128], acc);
        }
        pa2[tid] = acc;
    }
    __syncthreads();

    float tval = 0.f;
    if (tid < 128) {
        float pa = pa2[tid] + pa2[128 + tid];
        float ht = 0.f;
        for (int e = 0; e < 128; e++)
            ht = fmaf(es[e], g_WheadT[e * 128 + tid], ht);
        tval = fmaxf(pa + ht, 0.f) + es[tid];
    }

    float v = tval;
#pragma unroll
    for (int off = 16; off; off >>= 1) v += __shfl_xor_sync(0xffffffffu, v, off);
    if (lane == 0) red[w] = v;
    __syncthreads();
    float tot = 0.f;
#pragma unroll
    for (int i = 0; i < NWARP; i++) tot += red[i];
    float mu = tot * (1.f / 128.f);
    __syncthreads();

    float diff = (tid < 128) ? (tval - mu) : 0.f;
    float v2 = diff * diff;
#pragma unroll
    for (int off = 16; off; off >>= 1) v2 += __shfl_xor_sync(0xffffffffu, v2, off);
    if (lane == 0) red[w] = v2;
    __syncthreads();
    float tot2 = 0.f;
#pragma unroll
    for (int i = 0; i < NWARP; i++) tot2 += red[i];
    float var = tot2 * (1.f / 128.f);

    if (tid < 128)
        out[(size_t)sid * 128 + tid] =
            diff * rsqrtf(var + 1e-5f) * lnw[tid] + lnb[tid];
}

// ---------------- launch ----------------
extern "C" void kernel_launch(void* const* d_in, const int* in_sizes, int n_in,
                              void* d_out, int out_size) {
    const int*   ep    = (const int*)d_in[0];
    const int*   lconn = (const int*)d_in[1];
    const int*   rconn = (const int*)d_in[3];
    const float* emb   = (const float*)d_in[5];
    const float* Wv    = (const float*)d_in[6];
    const float* Wk    = (const float*)d_in[7];
    const float* Wq    = (const float*)d_in[8];
    const float* Ww    = (const float*)d_in[9];
    const float* Whead = (const float*)d_in[10];
    const float* lnw   = (const float*)d_in[11];
    const float* lnb   = (const float*)d_in[12];
    float* out = (float*)d_out;

    const int B = in_sizes[0] / 2;          // 1024
    const int SIDES = 2 * B;                // 2048

    static bool attr_done = false;
    if (!attr_done) {
        cudaFuncSetAttribute(mega, cudaFuncAttributeMaxDynamicSharedMemorySize, SM_TOT);
        attr_done = true;
    }

    prep_all<<<PREP_GRID, 256>>>(emb, Wv, Ww, Whead, Wk, Wq);
    mega<<<SIDES, NTHR, SM_TOT>>>(ep, lconn, rconn, emb, lnw, lnb, out);
}